// round 2
// baseline (speedup 1.0000x reference)
#include <cuda_runtime.h>

#define SEQ     8192
#define WIN     128
#define NHEADS  16
#define HDIM    64
#define HIDDEN  1024
#define NCHUNK  (SEQ / WIN)          // 64
#define KROWS   (3 * WIN)            // 384 key rows staged per block
#define THREADS 256

typedef unsigned long long ull;

// ---- packed f32x2 helpers (Blackwell) ----
__device__ __forceinline__ ull pk2(float lo, float hi) {
    ull r; asm("mov.b64 %0,{%1,%2};" : "=l"(r) : "f"(lo), "f"(hi)); return r;
}
__device__ __forceinline__ void upk2(ull v, float& lo, float& hi) {
    asm("mov.b64 {%0,%1},%2;" : "=f"(lo), "=f"(hi) : "l"(v));
}
__device__ __forceinline__ ull fma2(ull a, ull b, ull c) {
    ull d; asm("fma.rn.f32x2 %0,%1,%2,%3;" : "=l"(d) : "l"(a), "l"(b), "l"(c)); return d;
}
__device__ __forceinline__ ull add2(ull a, ull b) {
    ull d; asm("add.rn.f32x2 %0,%1,%2;" : "=l"(d) : "l"(a), "l"(b)); return d;
}

// Block = one (batch, head, 128-query chunk).
// smem: K tile [384][64] f32 then V tile [384][64] f32 (196608 B).
// 8 warps: group g = warp/2 owns local queries [g*32, g*32+32); the two warps
// of a group split the group's 288-row key window in half and later combine
// their (acc, l) partials (exact, since softmax is computed without max-shift).
__global__ void __launch_bounds__(THREADS, 1)
swa_kernel(const float* __restrict__ Q, const float* __restrict__ K,
           const float* __restrict__ V, float* __restrict__ O) {
    extern __shared__ float sm[];
    float* Ks = sm;
    float* Vs = sm + KROWS * HDIM;

    const int c = blockIdx.x & (NCHUNK - 1);
    const int h = (blockIdx.x >> 6) & (NHEADS - 1);
    const int b = blockIdx.x >> 10;
    const int tid = threadIdx.x;

    // ---- stage K/V window rows [c*128-128, c*128+256) into smem (zero-fill OOB)
    {
        const float4* K4 = (const float4*)K;
        const float4* V4 = (const float4*)V;
        const int t = tid & 15;
        const int base = c * WIN - WIN;
        for (int r = tid >> 4; r < KROWS; r += THREADS / 16) {
            const int kpos = base + r;
            float4 kv = make_float4(0.f, 0.f, 0.f, 0.f);
            float4 vv = make_float4(0.f, 0.f, 0.f, 0.f);
            if (kpos >= 0 && kpos < SEQ) {
                size_t gi = ((size_t)b * SEQ + kpos) * (HIDDEN / 4) + h * (HDIM / 4) + t;
                kv = K4[gi];
                vv = V4[gi];
            }
            ((float4*)Ks)[r * 16 + t] = kv;
            ((float4*)Vs)[r * 16 + t] = vv;
        }
    }
    __syncthreads();

    const int warp = tid >> 5, lane = tid & 31;
    const int g = warp >> 1, half = warp & 1;
    const int iq = g * 32 + lane;            // local query in chunk
    const int qpos = c * WIN + iq;           // global query position

    // ---- load q row into packed registers
    ull q2[HDIM / 2];
    {
        const float4* Q4 = (const float4*)Q + ((size_t)b * SEQ + qpos) * (HIDDEN / 4) + h * (HDIM / 4);
        #pragma unroll
        for (int t = 0; t < 16; t++) {
            float4 qv = Q4[t];
            q2[2 * t]     = pk2(qv.x, qv.y);
            q2[2 * t + 1] = pk2(qv.z, qv.w);
        }
    }

    ull acc[HDIM / 2];
    #pragma unroll
    for (int i = 0; i < HDIM / 2; i++) acc[i] = 0ull;
    float l = 0.f;

    const int rbase = g * 32;                // group's first smem key row
    // half 0 handles j in [0,144), half 1 j in [144,288); clamp to valid seq range
    int jlo = half ? 144 : 0;
    int jhi = half ? 288 : 144;
    {
        int jminSeq = WIN - c * WIN - rbase;           // kpos >= 0
        int jmaxSeq = SEQ - c * WIN + WIN - rbase;     // kpos <  SEQ
        if (jlo < jminSeq) jlo = jminSeq;
        if (jhi > jmaxSeq) jhi = jmaxSeq;
    }

    const ulonglong2* K2 = (const ulonglong2*)Ks;
    const ulonglong2* V2 = (const ulonglong2*)Vs;

    for (int j = jlo; j < jhi; j++) {
        const int r = rbase + j;
        const ulonglong2* kr = K2 + (size_t)r * 16;

        ull s0 = 0ull, s1 = 0ull, s2 = 0ull, s3 = 0ull;
        #pragma unroll
        for (int t = 0; t < 16; t += 2) {
            ulonglong2 ka = kr[t];
            ulonglong2 kb = kr[t + 1];
            s0 = fma2(q2[2 * t],     ka.x, s0);
            s1 = fma2(q2[2 * t + 1], ka.y, s1);
            s2 = fma2(q2[2 * t + 2], kb.x, s2);
            s3 = fma2(q2[2 * t + 3], kb.y, s3);
        }
        s0 = add2(s0, s1);
        s2 = add2(s2, s3);
        s0 = add2(s0, s2);
        float sa, sb;
        upk2(s0, sa, sb);
        const float s = sa + sb;

        // band: query iq attends rows [iq, iq+256]  <=>  j in [lane, lane+256]
        const bool valid = (j >= lane) && (j <= lane + 256);
        const float p = valid ? __expf(s) : 0.f;
        l += p;
        const ull p2 = pk2(p, p);

        const ulonglong2* vr = V2 + (size_t)r * 16;
        #pragma unroll
        for (int t = 0; t < 16; t++) {
            ulonglong2 va = vr[t];
            acc[2 * t]     = fma2(p2, va.x, acc[2 * t]);
            acc[2 * t + 1] = fma2(p2, va.y, acc[2 * t + 1]);
        }
    }

    // ---- combine the two half-warps' partials (exact: plain sums), write out
    __syncthreads();                    // all warps done with Ks/Vs; reuse smem
    float* P = sm;                      // [128 queries][65] (stride 65: conflict-free)
    if (half == 1) {
        float* row = P + (size_t)iq * 65;
        #pragma unroll
        for (int t = 0; t < HDIM / 2; t++) {
            float a0, a1;
            upk2(acc[t], a0, a1);
            row[2 * t] = a0;
            row[2 * t + 1] = a1;
        }
        row[64] = l;
    }
    __syncthreads();
    if (half == 0) {
        const float* row = P + (size_t)iq * 65;
        const float inv = 1.f / (l + row[64]);
        float4* O4 = (float4*)O + ((size_t)b * SEQ + qpos) * (HIDDEN / 4) + h * (HDIM / 4);
        #pragma unroll
        for (int t = 0; t < 16; t++) {
            float a0, a1, a2, a3;
            upk2(acc[2 * t],     a0, a1);
            upk2(acc[2 * t + 1], a2, a3);
            float4 o;
            o.x = (a0 + row[4 * t])     * inv;
            o.y = (a1 + row[4 * t + 1]) * inv;
            o.z = (a2 + row[4 * t + 2]) * inv;
            o.w = (a3 + row[4 * t + 3]) * inv;
            O4[t] = o;
        }
    }
}

extern "C" void kernel_launch(void* const* d_in, const int* in_sizes, int n_in,
                              void* d_out, int out_size) {
    const float* Q = (const float*)d_in[0];
    const float* K = (const float*)d_in[1];
    const float* V = (const float*)d_in[2];
    float* O = (float*)d_out;

    const int smem = KROWS * HDIM * 2 * (int)sizeof(float);   // 196608
    cudaFuncSetAttribute(swa_kernel, cudaFuncAttributeMaxDynamicSharedMemorySize, smem);

    const int B = 2;
    dim3 grid(B * NHEADS * NCHUNK);   // 2048 blocks: (b, h, chunk)
    swa_kernel<<<grid, THREADS, smem>>>(Q, K, V, O);
}